// round 9
// baseline (speedup 1.0000x reference)
#include <cuda_runtime.h>
#include <cuda_bf16.h>
#include <cstdint>

// Reference output is identically zero (min(.,0) before max(.,0) annihilates
// everything), so the kernel is a pure zero-fill of d_out (226.5 MB fp32).
//
// R6 evidence: instruction/occupancy overheads eliminated (regs 22, occ 80%,
// issue 4.7%) yet DRAM stuck at 58% while effective store-absorb = 6.4 TB/s.
// Hypothesis: DRAM-write-drain bound across graph replays; pinning ~104 MB of
// the output in L2 (evict_last) and streaming the rest (evict_first) cuts
// per-replay DRAM traffic. Neutral result would confirm the LTS absorb cap.
// (R7/R8 submissions hit broker infra failures before compile; never ran.)

__global__ void zero_fill_kernel(float4* __restrict__ out4, int n4, int a4) {
    uint64_t pol_last, pol_first;
    asm("createpolicy.fractional.L2::evict_last.b64 %0, 1.0;"  : "=l"(pol_last));
    asm("createpolicy.fractional.L2::evict_first.b64 %0, 1.0;" : "=l"(pol_first));

    const int bsz  = blockDim.x;
    const int span = gridDim.x * bsz * 4;
    int base = blockIdx.x * bsz * 4 + threadIdx.x;

    // Fast path: 4 independent coalesced STG.128 w/ cache-policy per iter.
    for (; base + 3 * bsz < n4; base += span) {
        #pragma unroll
        for (int j = 0; j < 4; j++) {
            int idx = base + j * bsz;
            uint64_t pol = (idx < a4) ? pol_last : pol_first;
            asm volatile(
                "st.global.L2::cache_hint.v4.f32 [%0], {%1,%1,%1,%1}, %2;"
                :: "l"(out4 + idx), "f"(0.0f), "l"(pol) : "memory");
        }
    }
    // Guarded epilogue tile.
    #pragma unroll
    for (int j = 0; j < 4; j++) {
        int idx = base + j * bsz;
        if (idx < n4) {
            uint64_t pol = (idx < a4) ? pol_last : pol_first;
            asm volatile(
                "st.global.L2::cache_hint.v4.f32 [%0], {%1,%1,%1,%1}, %2;"
                :: "l"(out4 + idx), "f"(0.0f), "l"(pol) : "memory");
        }
    }
}

__global__ void zero_tail_kernel(float* __restrict__ out, int start, int n) {
    int t = start + blockIdx.x * blockDim.x + threadIdx.x;
    if (t < n) out[t] = 0.f;
}

extern "C" void kernel_launch(void* const* d_in, const int* in_sizes, int n_in,
                              void* d_out, int out_size) {
    (void)d_in; (void)in_sizes; (void)n_in;

    int n  = out_size;          // fp32 elements (56.6M < 2^31)
    int n4 = n >> 2;            // float4 chunks
    // ~104 MB pinned-resident region (L2 = 126 MB on this part).
    long long a_bytes = 104LL * 1024 * 1024;
    long long a4_ll = a_bytes / 16;
    int a4 = (a4_ll > n4) ? n4 : (int)a4_ll;

    const int threads = 256;
    int blocks = 148 * 16;
    long long needed = ((long long)n4 + threads * 4 - 1) / (threads * 4);
    if (needed < blocks) blocks = (int)(needed > 0 ? needed : 1);
    zero_fill_kernel<<<blocks, threads>>>((float4*)d_out, n4, a4);

    int tail_start = n4 << 2;
    if (tail_start < n) {
        zero_tail_kernel<<<1, 128>>>((float*)d_out, tail_start, n);
    }
}

// round 11
// speedup vs baseline: 1.0008x; 1.0008x over previous
#include <cuda_runtime.h>
#include <cuda_bf16.h>
#include <cstdint>

// Reference output is identically zero: the epilogue min(max(min(yn,0),0),1)
// clamps everything to exactly 0 before the dropout scale. Optimal kernel is
// a pure zero-fill of d_out (226.5 MB fp32 stores).
//
// Measured across R2/R5/R6/R9: every variant saturates at 6.3-6.5 TB/s
// effective store absorb == the chip-wide LTS throughput cap (~6300 B/cyc,
// path-independent). L2 residency hints (R9) were neutral; DRAM% is not the
// binding resource. This version = best measured ingredients only:
//   4x independent coalesced STG.128 / iter (R5's store shape, fastest)
//   int32 indexing (R6: regs 22, occ 80%)
//   no cache hints, single kernel launch.
// (R10 submission of this kernel hit a broker infra failure; never ran.)

__global__ void zero_fill_kernel(float* __restrict__ out, int n) {
    int n4 = n >> 2;                 // float4 chunks
    float4* __restrict__ out4 = reinterpret_cast<float4*>(out);
    const float4 z = make_float4(0.f, 0.f, 0.f, 0.f);

    const int bsz  = blockDim.x;
    const int span = gridDim.x * bsz * 4;
    int base = blockIdx.x * bsz * 4 + threadIdx.x;

    // Fast path: 4 independent unguarded coalesced STG.128 per iteration.
    for (; base + 3 * bsz < n4; base += span) {
        out4[base]           = z;
        out4[base + bsz]     = z;
        out4[base + 2 * bsz] = z;
        out4[base + 3 * bsz] = z;
    }
    // Guarded epilogue tile (last, possibly partial, stride sequence).
    #pragma unroll
    for (int j = 0; j < 4; j++) {
        int idx = base + j * bsz;
        if (idx < n4) out4[idx] = z;
    }
    // Scalar tail (n not divisible by 4) — no-op for this problem size.
    int t = (n4 << 2) + blockIdx.x * bsz + threadIdx.x;
    if (t < n) out[t] = 0.f;
}

extern "C" void kernel_launch(void* const* d_in, const int* in_sizes, int n_in,
                              void* d_out, int out_size) {
    (void)d_in; (void)in_sizes; (void)n_in;

    int n  = out_size;   // fp32 elements (56,623,104 < 2^31)
    int n4 = n >> 2;     // float4 chunks

    const int threads = 256;
    int blocks = 148 * 16;
    long long needed = ((long long)n4 + threads * 4 - 1) / (threads * 4);
    if (needed < blocks) blocks = (int)(needed > 0 ? needed : 1);

    zero_fill_kernel<<<blocks, threads>>>((float*)d_out, n);
}